// round 5
// baseline (speedup 1.0000x reference)
#include <cuda_runtime.h>
#include <cuda_bf16.h>
#include <cstddef>

// Problem constants
constexpr int BB  = 8;
constexpr int SS  = 4096;
constexpr int DD  = 1024;
constexpr int HH  = 16;
constexpr int DHH = 64;
constexpr int MTOK = BB * SS;          // 32768 tokens
constexpr int NGEMM = DD;              // 1024
constexpr int KGEMM = DD;              // 1024

// Scratch (device globals: no allocation allowed in kernel_launch)
__device__ float g_q[(size_t)MTOK * DD];
__device__ float g_k[(size_t)MTOK * DD];
__device__ float g_v[(size_t)MTOK * DD];
__device__ float g_ctx[(size_t)MTOK * DD];

// ---------------------------------------------------------------------------
// SGEMM (NT): C[m][n] = sum_k A[m][k] * B[n][k] + bias[n]
// A: [M,K] row-major, B: [N,K] row-major (i.e. torch Linear weight), C: [M,N]
// BM=128, BN=128, BK=8, 256 threads, 8x8 per-thread micro-tile.
// M=32768, N=1024, K=1024 all divide tiles exactly -> no bounds checks.
// ---------------------------------------------------------------------------
#define BM 128
#define BN 128
#define BK 8
#define TM 8
#define TN 8

__global__ __launch_bounds__(256, 2)
void sgemm_nt_bias(const float* __restrict__ A,
                   const float* __restrict__ B,
                   const float* __restrict__ bias,
                   float* __restrict__ C,
                   int M, int N, int K)
{
    __shared__ float As[BK][BM];
    __shared__ float Bs[BK][BN];

    const int tid = threadIdx.x;        // 0..255
    const int m0 = blockIdx.y * BM;
    const int n0 = blockIdx.x * BN;
    const int tx = tid & 15;            // 0..15 -> n sub-block
    const int ty = tid >> 4;            // 0..15 -> m sub-block

    // Tile-load mapping: each thread loads one float4 of A and one of B
    const int lr = tid >> 1;            // 0..127 row within tile
    const int lc = (tid & 1) * 4;       // 0 or 4 col within BK

    const float* Ar = A + (size_t)(m0 + lr) * K + lc;
    const float* Br = B + (size_t)(n0 + lr) * K + lc;

    float acc[TM][TN];
    #pragma unroll
    for (int i = 0; i < TM; i++)
        #pragma unroll
        for (int j = 0; j < TN; j++) acc[i][j] = 0.0f;

    for (int k0 = 0; k0 < K; k0 += BK) {
        float4 av = *(const float4*)(Ar + k0);
        float4 bv = *(const float4*)(Br + k0);
        As[lc + 0][lr] = av.x;
        As[lc + 1][lr] = av.y;
        As[lc + 2][lr] = av.z;
        As[lc + 3][lr] = av.w;
        Bs[lc + 0][lr] = bv.x;
        Bs[lc + 1][lr] = bv.y;
        Bs[lc + 2][lr] = bv.z;
        Bs[lc + 3][lr] = bv.w;
        __syncthreads();

        #pragma unroll
        for (int kk = 0; kk < BK; kk++) {
            float a[TM], b[TN];
            // vectorized shared loads (contiguous, broadcast-friendly)
            *(float4*)&a[0] = *(const float4*)&As[kk][ty * TM];
            *(float4*)&a[4] = *(const float4*)&As[kk][ty * TM + 4];
            *(float4*)&b[0] = *(const float4*)&Bs[kk][tx * TN];
            *(float4*)&b[4] = *(const float4*)&Bs[kk][tx * TN + 4];
            #pragma unroll
            for (int i = 0; i < TM; i++)
                #pragma unroll
                for (int j = 0; j < TN; j++)
                    acc[i][j] = fmaf(a[i], b[j], acc[i][j]);
        }
        __syncthreads();
    }

    // Epilogue: add bias, vectorized stores
    #pragma unroll
    for (int i = 0; i < TM; i++) {
        const int m = m0 + ty * TM + i;
        float* Crow = C + (size_t)m * N + n0 + tx * TN;
        #pragma unroll
        for (int j = 0; j < TN; j += 4) {
            const int nb = n0 + tx * TN + j;
            float4 o;
            o.x = acc[i][j + 0] + bias[nb + 0];
            o.y = acc[i][j + 1] + bias[nb + 1];
            o.z = acc[i][j + 2] + bias[nb + 2];
            o.w = acc[i][j + 3] + bias[nb + 3];
            *(float4*)(Crow + j) = o;
        }
    }
}

// ---------------------------------------------------------------------------
// Per-token attention over the HEAD axis (per the reference's quirk):
//   scores[h][g] = (q[h] . k[g]) / 8      (16x16, dot over DH=64)
//   probs = softmax over g
//   ctx[h][d]   = sum_g probs[h][g] * v[g][d]
// One warp per token, 2 warps per block.
// ---------------------------------------------------------------------------
constexpr int WPB = 2;         // warps (tokens) per block
constexpr int RPAD = 65;       // padded row stride (floats) -> conflict-free

__global__ __launch_bounds__(WPB * 32)
void attn_kernel(const float* __restrict__ q,
                 const float* __restrict__ k,
                 const float* __restrict__ v,
                 float* __restrict__ ctx)
{
    __shared__ float sq[WPB][HH * RPAD];
    __shared__ float sk[WPB][HH * RPAD];
    __shared__ float sv[WPB][HH * RPAD];
    __shared__ float sp[WPB][HH][17];   // scores/probs, padded

    const int w    = threadIdx.x >> 5;
    const int lane = threadIdx.x & 31;
    const size_t token = (size_t)blockIdx.x * WPB + w;

    const float* qt = q + token * DD;
    const float* kt = k + token * DD;
    const float* vt = v + token * DD;

    // Stage q,k,v (1024 floats each) into padded shared
    #pragma unroll
    for (int i = 0; i < 8; i++) {
        const int e   = i * 128 + lane * 4;  // linear element idx
        const int row = e >> 6;              // /64
        const int col = e & 63;
        const float4 qv = *(const float4*)(qt + e);
        const float4 kv = *(const float4*)(kt + e);
        const float4 vv = *(const float4*)(vt + e);
        float* sqr = &sq[w][row * RPAD + col];
        float* skr = &sk[w][row * RPAD + col];
        float* svr = &sv[w][row * RPAD + col];
        sqr[0] = qv.x; sqr[1] = qv.y; sqr[2] = qv.z; sqr[3] = qv.w;
        skr[0] = kv.x; skr[1] = kv.y; skr[2] = kv.z; skr[3] = kv.w;
        svr[0] = vv.x; svr[1] = vv.y; svr[2] = vv.z; svr[3] = vv.w;
    }
    __syncwarp();

    // Scores: 256 (h,g) pairs, 8 per lane
    #pragma unroll
    for (int i = 0; i < 8; i++) {
        const int p = i * 32 + lane;
        const int h = p >> 4;
        const int g = p & 15;
        const float* qr = &sq[w][h * RPAD];
        const float* kr = &sk[w][g * RPAD];
        float accv = 0.0f;
        #pragma unroll
        for (int d = 0; d < DHH; d++)
            accv = fmaf(qr[d], kr[d], accv);
        sp[w][h][g] = accv * 0.125f;     // 1/sqrt(64)
    }
    __syncwarp();

    // Softmax over g: lanes 0..15 each own one h-row
    if (lane < HH) {
        float mx = -1e30f;
        #pragma unroll
        for (int g = 0; g < HH; g++) mx = fmaxf(mx, sp[w][lane][g]);
        float e[HH];
        float s = 0.0f;
        #pragma unroll
        for (int g = 0; g < HH; g++) { e[g] = __expf(sp[w][lane][g] - mx); s += e[g]; }
        const float inv = 1.0f / s;
        #pragma unroll
        for (int g = 0; g < HH; g++) sp[w][lane][g] = e[g] * inv;
    }
    __syncwarp();

    // Context: lane owns columns d=lane and d=lane+32
    float* ct = ctx + token * DD;
    #pragma unroll
    for (int h = 0; h < HH; h++) {
        float a0 = 0.0f, a1 = 0.0f;
        #pragma unroll
        for (int g = 0; g < HH; g++) {
            const float p = sp[w][h][g];
            a0 = fmaf(p, sv[w][g * RPAD + lane],      a0);
            a1 = fmaf(p, sv[w][g * RPAD + lane + 32], a1);
        }
        ct[h * DHH + lane]      = a0;
        ct[h * DHH + lane + 32] = a1;
    }
}

// ---------------------------------------------------------------------------
// Launch
// ---------------------------------------------------------------------------
extern "C" void kernel_launch(void* const* d_in, const int* in_sizes, int n_in,
                              void* d_out, int out_size)
{
    const float* x  = (const float*)d_in[0];
    const float* wq = (const float*)d_in[1];
    const float* bq = (const float*)d_in[2];
    const float* wk = (const float*)d_in[3];
    const float* bk = (const float*)d_in[4];
    const float* wv = (const float*)d_in[5];
    const float* bv = (const float*)d_in[6];
    const float* wo = (const float*)d_in[7];
    const float* bo = (const float*)d_in[8];
    float* out = (float*)d_out;

    float *q, *k, *v, *ctx;
    cudaGetSymbolAddress((void**)&q,   g_q);
    cudaGetSymbolAddress((void**)&k,   g_k);
    cudaGetSymbolAddress((void**)&v,   g_v);
    cudaGetSymbolAddress((void**)&ctx, g_ctx);

    dim3 gblk(256);
    dim3 ggrid(NGEMM / BN, MTOK / BM);   // (8, 256)

    sgemm_nt_bias<<<ggrid, gblk>>>(x, wq, bq, q, MTOK, NGEMM, KGEMM);
    sgemm_nt_bias<<<ggrid, gblk>>>(x, wk, bk, k, MTOK, NGEMM, KGEMM);
    sgemm_nt_bias<<<ggrid, gblk>>>(x, wv, bv, v, MTOK, NGEMM, KGEMM);

    attn_kernel<<<MTOK / WPB, WPB * 32>>>(q, k, v, ctx);

    sgemm_nt_bias<<<ggrid, gblk>>>(ctx, wo, bo, out, MTOK, NGEMM, KGEMM);
}

// round 7
// speedup vs baseline: 3.2058x; 3.2058x over previous
#include <cuda_runtime.h>
#include <cuda_bf16.h>
#include <cstdint>
#include <cstddef>

// Problem constants
constexpr int BB  = 8;
constexpr int SS  = 4096;
constexpr int DD  = 1024;
constexpr int HH  = 16;
constexpr int DHH = 64;
constexpr int MTOK = BB * SS;          // 32768 tokens
constexpr int K3   = 3 * DD;           // 3072 packed-K (hi|lo|hi vs hi|hi|lo)

// ---------------------------------------------------------------------------
// Scratch (device globals: no allocation allowed anywhere)
// ---------------------------------------------------------------------------
__device__ float g_q  [(size_t)MTOK * DD];
__device__ float g_k  [(size_t)MTOK * DD];
__device__ float g_v  [(size_t)MTOK * DD];
__device__ float g_ctx[(size_t)MTOK * DD];
__device__ __nv_bfloat16 g_xs [(size_t)MTOK * K3];   // x   split  [hi|lo|hi]
__device__ __nv_bfloat16 g_cs [(size_t)MTOK * K3];   // ctx split  [hi|lo|hi]
__device__ __nv_bfloat16 g_wqs[(size_t)DD * K3];     // weights    [hi|hi|lo]
__device__ __nv_bfloat16 g_wks[(size_t)DD * K3];
__device__ __nv_bfloat16 g_wvs[(size_t)DD * K3];
__device__ __nv_bfloat16 g_wos[(size_t)DD * K3];

// ---------------------------------------------------------------------------
// Helpers
// ---------------------------------------------------------------------------
__device__ __forceinline__ uint32_t smem_u32(const void* p) {
    uint32_t a;
    asm("{ .reg .u64 t; cvta.to.shared.u64 t, %1; cvt.u32.u64 %0, t; }"
        : "=r"(a) : "l"(p));
    return a;
}

__device__ __forceinline__ void cp16(uint32_t dst, const void* src) {
    asm volatile("cp.async.cg.shared.global [%0], [%1], 16;"
                 :: "r"(dst), "l"(src) : "memory");
}

__device__ __forceinline__ uint32_t swz(uint32_t off) {
    return off ^ ((off >> 3) & 0x70);   // SW128 within 1024B blocks
}

__device__ __forceinline__ void ldsm4(uint32_t r[4], uint32_t addr) {
    asm volatile("ldmatrix.sync.aligned.m8n8.x4.shared.b16 {%0,%1,%2,%3}, [%4];"
                 : "=r"(r[0]), "=r"(r[1]), "=r"(r[2]), "=r"(r[3]) : "r"(addr));
}

__device__ __forceinline__ void mma16816(float d[4], const uint32_t a[4],
                                         uint32_t b0, uint32_t b1) {
    asm volatile(
        "mma.sync.aligned.m16n8k16.row.col.f32.bf16.bf16.f32 "
        "{%0,%1,%2,%3}, {%4,%5,%6,%7}, {%8,%9}, {%0,%1,%2,%3};"
        : "+f"(d[0]), "+f"(d[1]), "+f"(d[2]), "+f"(d[3])
        : "r"(a[0]), "r"(a[1]), "r"(a[2]), "r"(a[3]), "r"(b0), "r"(b1));
}

// ---------------------------------------------------------------------------
// Split-precision conversion:  act pattern [hi|lo|hi],  wt pattern [hi|hi|lo]
// ---------------------------------------------------------------------------
struct alignas(16) B8 { __nv_bfloat16 v[8]; };

__global__ __launch_bounds__(256)
void split3(const float* __restrict__ src, __nv_bfloat16* __restrict__ dst, int act)
{
    const size_t idx = ((size_t)blockIdx.x * 256 + threadIdx.x) * 8;
    const size_t row = idx >> 10;
    const int    col = (int)(idx & 1023);
    const float4 a = *(const float4*)(src + idx);
    const float4 b = *(const float4*)(src + idx + 4);
    float f[8] = {a.x, a.y, a.z, a.w, b.x, b.y, b.z, b.w};
    B8 ph, pl;
    #pragma unroll
    for (int i = 0; i < 8; i++) {
        __nv_bfloat16 h = __float2bfloat16(f[i]);
        ph.v[i] = h;
        pl.v[i] = __float2bfloat16(f[i] - __bfloat162float(h));
    }
    __nv_bfloat16* base = dst + row * K3 + col;
    *(B8*)(base)        = ph;
    *(B8*)(base + 1024) = act ? pl : ph;
    *(B8*)(base + 2048) = act ? ph : pl;
}

// ---------------------------------------------------------------------------
// bf16 mma.sync GEMM (NT): C[m][n] = sum_k A[m][k]*B[n][k] + bias[n]
// A:[MTOK,K3] bf16, B:[DD,K3] bf16, C:[MTOK,DD] fp32.
// Tile 128x256, BK=64 (128B rows, SW128 swizzle), 8 warps (2x4) of 64x64,
// 3-stage cp.async pipeline, ldmatrix fragments, m16n8k16 HMMA.
// ---------------------------------------------------------------------------
constexpr int GBM = 128, GBN = 256, GBK = 64;
constexpr int STAGES = 3;
constexpr int NCH = K3 / GBK;                 // 48
constexpr int ASZ = GBM * 128;                // 16384 B / stage
constexpr int BSZ = GBN * 128;                // 32768 B / stage
constexpr int STG = ASZ + BSZ;                // 49152
constexpr int GEMM_SMEM = STAGES * STG;       // 147456

__global__ __launch_bounds__(256, 1)
void gemm_mma(const __nv_bfloat16* __restrict__ A,
              const __nv_bfloat16* __restrict__ B,
              const float* __restrict__ bias,
              float* __restrict__ C)
{
    extern __shared__ char smem[];
    const uint32_t sb = smem_u32(smem);
    const int tid  = threadIdx.x;
    const int wid  = tid >> 5;
    const int lane = tid & 31;
    const int m0 = blockIdx.y * GBM;
    const int n0 = blockIdx.x * GBN;
    const int wm = (wid >> 2) * 64;           // warp m offset in tile
    const int wn = (wid & 3) * 64;            // warp n offset in tile

    float acc[4][8][4];
    #pragma unroll
    for (int i = 0; i < 4; i++)
        #pragma unroll
        for (int j = 0; j < 8; j++)
            #pragma unroll
            for (int c = 0; c < 4; c++) acc[i][j][c] = 0.0f;

    auto load_stage = [&](int i, int s) {
        const int k0 = i * GBK;
        const uint32_t ab = sb + s * STG;
        const uint32_t bb = ab + ASZ;
        #pragma unroll
        for (int j = 0; j < 12; j++) {
            const int c  = tid + j * 256;
            const int cc = c & 7;
            if (c < 1024) {
                const int r = c >> 3;          // A rows 0..127
                cp16(ab + swz((uint32_t)(r * 128 + cc * 16)),
                     A + (size_t)(m0 + r) * K3 + k0 + cc * 8);
            } else {
                const int r = (c - 1024) >> 3; // B rows 0..255
                cp16(bb + swz((uint32_t)(r * 128 + cc * 16)),
                     B + (size_t)(n0 + r) * K3 + k0 + cc * 8);
            }
        }
        asm volatile("cp.async.commit_group;" ::: "memory");
    };

    load_stage(0, 0);
    load_stage(1, 1);

    // ldmatrix per-lane source rows (within warp tile), SW128-swizzled later
    const int arow = wm + (lane & 15);         // A: lanes 0-15 rows, 16-31 k+8
    const int akb  = (lane >> 4) * 16;         // 8 bf16 = 16B half-step in k
    const int brow = wn + (lane & 7) + ((lane >> 4) << 3); // B: n8 pairs
    const int bkb  = ((lane >> 3) & 1) * 16;

    for (int i = 0; i < NCH; i++) {
        asm volatile("cp.async.wait_group 1;" ::: "memory");
        __syncthreads();
        const int s = i % STAGES;
        const uint32_t ab = sb + s * STG;
        const uint32_t bb = ab + ASZ;

        #pragma unroll
        for (int kk = 0; kk < 4; kk++) {       // 4 x k16 per 64-chunk
            const int c0 = kk * 32;            // byte offset of k16 step
            uint32_t af[4][4], bf[4][4];
            #pragma unroll
            for (int mi = 0; mi < 4; mi++)
                ldsm4(af[mi], ab + swz((uint32_t)((arow + mi * 16) * 128 + c0 + akb)));
            #pragma unroll
            for (int nj = 0; nj < 4; nj++)
                ldsm4(bf[nj], bb + swz((uint32_t)((brow + nj * 16) * 128 + c0 + bkb)));
            #pragma unroll
            for (int mi = 0; mi < 4; mi++)
                #pragma unroll
                for (int nj = 0; nj < 4; nj++) {
                    mma16816(acc[mi][2 * nj],     af[mi], bf[nj][0], bf[nj][1]);
                    mma16816(acc[mi][2 * nj + 1], af[mi], bf[nj][2], bf[nj][3]);
                }
        }
        if (i + 2 < NCH) load_stage(i + 2, (i + 2) % STAGES);
    }

    // Epilogue: fragment layout c0,c1 -> (row + lane/4, col + 2*(lane%4));
    // c2,c3 -> row+8. Add bias, float2 stores.
    const int rbase = m0 + wm + (lane >> 2);
    const int cbase = n0 + wn + 2 * (lane & 3);
    float2 bb2[8];
    #pragma unroll
    for (int nj = 0; nj < 8; nj++) {
        bb2[nj].x = bias[cbase + nj * 8];
        bb2[nj].y = bias[cbase + nj * 8 + 1];
    }
    #pragma unroll
    for (int mi = 0; mi < 4; mi++) {
        #pragma unroll
        for (int nj = 0; nj < 8; nj++) {
            const int cc = cbase + nj * 8;
            float2 v0 = { acc[mi][nj][0] + bb2[nj].x, acc[mi][nj][1] + bb2[nj].y };
            float2 v1 = { acc[mi][nj][2] + bb2[nj].x, acc[mi][nj][3] + bb2[nj].y };
            *(float2*)(C + (size_t)(rbase + mi * 16)     * DD + cc) = v0;
            *(float2*)(C + (size_t)(rbase + mi * 16 + 8) * DD + cc) = v1;
        }
    }
}

// ---------------------------------------------------------------------------
// Per-token attention over the HEAD axis (reference quirk), unchanged.
// ---------------------------------------------------------------------------
constexpr int WPB = 2;
constexpr int RPAD = 65;

__global__ __launch_bounds__(WPB * 32)
void attn_kernel(const float* __restrict__ q,
                 const float* __restrict__ k,
                 const float* __restrict__ v,
                 float* __restrict__ ctx)
{
    __shared__ float sq[WPB][HH * RPAD];
    __shared__ float sk[WPB][HH * RPAD];
    __shared__ float sv[WPB][HH * RPAD];
    __shared__ float sp[WPB][HH][17];

    const int w    = threadIdx.x >> 5;
    const int lane = threadIdx.x & 31;
    const size_t token = (size_t)blockIdx.x * WPB + w;

    const float* qt = q + token * DD;
    const float* kt = k + token * DD;
    const float* vt = v + token * DD;

    #pragma unroll
    for (int i = 0; i < 8; i++) {
        const int e   = i * 128 + lane * 4;
        const int row = e >> 6;
        const int col = e & 63;
        const float4 qv = *(const float4*)(qt + e);
        const float4 kv = *(const float4*)(kt + e);
        const float4 vv = *(const float4*)(vt + e);
        float* sqr = &sq[w][row * RPAD + col];
        float* skr = &sk[w][row * RPAD + col];
        float* svr = &sv[w][row * RPAD + col];
        sqr[0] = qv.x; sqr[1] = qv.y; sqr[2] = qv.z; sqr[3] = qv.w;
        skr[0] = kv.x; skr[1] = kv.y; skr[2] = kv.z; skr[3] = kv.w;
        svr[0] = vv.x; svr[1] = vv.y; svr[2] = vv.z; svr[3] = vv.w;
    }
    __syncwarp();

    #pragma unroll
    for (int i = 0; i < 8; i++) {
        const int p = i * 32 + lane;
        const int h = p >> 4;
        const int g = p & 15;
        const float* qr = &sq[w][h * RPAD];
        const float* kr = &sk[w][g * RPAD];
        float accv = 0.0f;
        #pragma unroll
        for (int d = 0; d < DHH; d++)
            accv = fmaf(qr[d], kr[d], accv);
        sp[w][h][g] = accv * 0.125f;
    }
    __syncwarp();

    if (lane < HH) {
        float mx = -1e30f;
        #pragma unroll
        for (int g = 0; g < HH; g++) mx = fmaxf(mx, sp[w][lane][g]);
        float e[HH];
        float s = 0.0f;
        #pragma unroll
        for (int g = 0; g < HH; g++) { e[g] = __expf(sp[w][lane][g] - mx); s += e[g]; }
        const float inv = 1.0f / s;
        #pragma unroll
        for (int g = 0; g < HH; g++) sp[w][lane][g] = e[g] * inv;
    }
    __syncwarp();

    float* ct = ctx + token * DD;
    #pragma unroll
    for (int h = 0; h < HH; h++) {
        float a0 = 0.0f, a1 = 0.0f;
        #pragma unroll
        for (int g = 0; g < HH; g++) {
            const float p = sp[w][h][g];
            a0 = fmaf(p, sv[w][g * RPAD + lane],      a0);
            a1 = fmaf(p, sv[w][g * RPAD + lane + 32], a1);
        }
        ct[h * DHH + lane]      = a0;
        ct[h * DHH + lane + 32] = a1;
    }
}

// ---------------------------------------------------------------------------
// Launch
// ---------------------------------------------------------------------------
extern "C" void kernel_launch(void* const* d_in, const int* in_sizes, int n_in,
                              void* d_out, int out_size)
{
    const float* x  = (const float*)d_in[0];
    const float* wq = (const float*)d_in[1];
    const float* bq = (const float*)d_in[2];
    const float* wk = (const float*)d_in[3];
    const float* bk = (const float*)d_in[4];
    const float* wv = (const float*)d_in[5];
    const float* bv = (const float*)d_in[6];
    const float* wo = (const float*)d_in[7];
    const float* bo = (const float*)d_in[8];
    float* out = (float*)d_out;

    float *q, *k, *v, *ctx;
    __nv_bfloat16 *xs, *cs, *wqs, *wks, *wvs, *wos;
    cudaGetSymbolAddress((void**)&q,   g_q);
    cudaGetSymbolAddress((void**)&k,   g_k);
    cudaGetSymbolAddress((void**)&v,   g_v);
    cudaGetSymbolAddress((void**)&ctx, g_ctx);
    cudaGetSymbolAddress((void**)&xs,  g_xs);
    cudaGetSymbolAddress((void**)&cs,  g_cs);
    cudaGetSymbolAddress((void**)&wqs, g_wqs);
    cudaGetSymbolAddress((void**)&wks, g_wks);
    cudaGetSymbolAddress((void**)&wvs, g_wvs);
    cudaGetSymbolAddress((void**)&wos, g_wos);

    cudaFuncSetAttribute(gemm_mma,
                         cudaFuncAttributeMaxDynamicSharedMemorySize, GEMM_SMEM);

    const int act_blocks = (int)(((size_t)MTOK * DD / 8) / 256);   // 16384
    const int wt_blocks  = (int)(((size_t)DD * DD / 8) / 256);     // 512

    split3<<<act_blocks, 256>>>(x,  xs,  1);
    split3<<<wt_blocks,  256>>>(wq, wqs, 0);
    split3<<<wt_blocks,  256>>>(wk, wks, 0);
    split3<<<wt_blocks,  256>>>(wv, wvs, 0);
    split3<<<wt_blocks,  256>>>(wo, wos, 0);

    dim3 gg(DD / GBN, MTOK / GBM);   // (4, 256)
    gemm_mma<<<gg, 256, GEMM_SMEM>>>(xs, wqs, bq, q);
    gemm_mma<<<gg, 256, GEMM_SMEM>>>(xs, wks, bk, k);
    gemm_mma<<<gg, 256, GEMM_SMEM>>>(xs, wvs, bv, v);

    attn_kernel<<<MTOK / WPB, WPB * 32>>>(q, k, v, ctx);

    split3<<<act_blocks, 256>>>(ctx, cs, 1);
    gemm_mma<<<gg, 256, GEMM_SMEM>>>(cs, wos, bo, out);
}